// round 1
// baseline (speedup 1.0000x reference)
#include <cuda_runtime.h>

// MertonJumpDiffusion: paths[p, 0] = S0; paths[p, t+1] = S0 * exp(cumsum_t(log_ret))
// log_ret[t,p] = drift[t] + SIGMA*sqrt(DT)*z_diff[t,p] + sqrt(n_jumps[t,p])*SIGMA_J*z_jump[t,p]
// (MU_J = 0, so the nj*MU_J term vanishes.)

#define N_STEPS   2048
#define N_PATHS   32768
#define TPB       256
#define TILE      32
#define N_CHUNKS  (N_STEPS / TILE)
#define OUT_COLS  (N_STEPS + 1)

__device__ __forceinline__ float sqrt_approx(float x) {
    // sqrt.approx.f32: sqrt(+0) = +0 (safe for n_jumps == 0, unlike n * rsqrt(n))
    float y;
    asm("sqrt.approx.f32 %0, %1;" : "=f"(y) : "f"(x));
    return y;
}

__global__ __launch_bounds__(TPB) void merton_kernel(
    const float* __restrict__ S0p,
    const float* __restrict__ zd,
    const float* __restrict__ zj,
    const int*   __restrict__ njp,
    float*       __restrict__ out)
{
    __shared__ float drift_s[N_STEPS];          // 8 KB
    __shared__ float buf[TPB][TILE + 1];        // 33.8 KB, padded: conflict-free fill + drain

    const int tid   = threadIdx.x;
    const int pbase = blockIdx.x * TPB;
    const int p     = pbase + tid;
    const int wid   = tid >> 5;
    const int lane  = tid & 31;

    const float DT    = 1.0f / 2048.0f;
    const float KAPPA = 0.04602785990f;                 // exp(0.045) - 1, fp32
    // Matches reference fp32 order: SIGMA * fl(sqrt(DT))
    const float CDIFF = 0.2f * 0.02209708691f;          // = SIGMA * sqrt(DT)
    const float SJ    = 0.3f;                           // SIGMA_J

    // Per-step drift table: drift[t] = -(lam(t) * KAPPA) * DT
    for (int i = tid; i < N_STEPS; i += TPB) {
        float t   = (float)i * DT;
        float lam = 0.1f + 0.9f * expf(-0.01f * t);
        drift_s[i] = (0.0f - lam * KAPPA) * DT;
    }

    const float s0 = S0p[0];
    __syncthreads();

    // Column 0: S0 * exp(0). One-time strided write (1 MB of sectors), negligible.
    out[p * OUT_COLS] = s0;

    float acc = 0.0f;

    for (int c = 0; c < N_CHUNKS; ++c) {
        const int tbase = c * TILE;

        // --- Fill phase: coalesced streaming loads, sequential fp32 scan ---
        #pragma unroll
        for (int s = 0; s < TILE; ++s) {
            const int t   = tbase + s;
            const int idx = t * N_PATHS + p;           // < 2^26, int math is fine
            float z1 = zd[idx];
            float z2 = zj[idx];
            float nf = (float)njp[idx];
            acc += drift_s[t] + CDIFF * z1 + sqrt_approx(nf) * SJ * z2;
            buf[tid][s] = s0 * __expf(acc);
        }
        __syncthreads();

        // --- Drain phase: warp-per-row, 32 consecutive floats per store (coalesced) ---
        #pragma unroll 8
        for (int r = 0; r < TILE; ++r) {
            const int row = wid * TILE + r;            // 8 warps x 32 rows = 256 paths
            out[(pbase + row) * OUT_COLS + 1 + tbase + lane] = buf[row][lane];
        }
        __syncthreads();
    }
}

extern "C" void kernel_launch(void* const* d_in, const int* in_sizes, int n_in,
                              void* d_out, int out_size)
{
    const float* S0 = (const float*)d_in[0];
    const float* zd = (const float*)d_in[1];
    const float* zj = (const float*)d_in[2];
    const int*   nj = (const int*)  d_in[3];
    float*       out = (float*)d_out;

    merton_kernel<<<N_PATHS / TPB, TPB>>>(S0, zd, zj, nj, out);
}

// round 2
// speedup vs baseline: 2.0174x; 2.0174x over previous
#include <cuda_runtime.h>

// Merton jump diffusion:
//   paths[p,0]   = S0
//   paths[p,t+1] = S0 * exp( sum_{u<=t} log_ret[u,p] )
//   log_ret[t,p] = drift[t] + SIGMA*sqrt(DT)*zd[t,p] + sqrt(nj[t,p])*SIGMA_J*zj[t,p]
// MU_J = 0. nj is Poisson(lam*dt <= ~5e-4) -> tiny ints -> sqrt via SMEM table.

#define N_STEPS   2048
#define N_PATHS   32768
#define TPB       128
#define TILE      32
#define N_CHUNKS  (N_STEPS / TILE)
#define OUT_COLS  (N_STEPS + 1)
#define JT_SIZE   32

__global__ __launch_bounds__(TPB) void merton_kernel(
    const float* __restrict__ S0p,
    const float* __restrict__ zd,
    const float* __restrict__ zj,
    const int*   __restrict__ njp,
    float*       __restrict__ out)
{
    __shared__ float drift_s[N_STEPS];        // 8 KB: per-step drift
    __shared__ float jtab[JT_SIZE];           // sqrt(n)*SIGMA_J table
    __shared__ float buf[TPB][TILE + 1];      // 16.5 KB staging, padded (conflict-free)

    const int tid   = threadIdx.x;
    const int pbase = blockIdx.x * TPB;
    const int p     = pbase + tid;
    const int wid   = tid >> 5;
    const int lane  = tid & 31;

    const float DT    = 1.0f / 2048.0f;
    const float KAPPA = 0.04602785990f;              // exp(0.045) - 1 (fp32)
    const float CDIFF = 0.2f * 0.02209708691f;       // SIGMA * fl(sqrt(DT)), ref fp32 order

    // Per-step drift table: drift[t] = -(lam(t) * KAPPA) * DT
    for (int i = tid; i < N_STEPS; i += TPB) {
        float t   = (float)i * DT;
        float lam = 0.1f + 0.9f * expf(-0.01f * t);
        drift_s[i] = (0.0f - lam * KAPPA) * DT;
    }
    if (tid < JT_SIZE) jtab[tid] = sqrtf((float)tid) * 0.3f;

    const float s0 = S0p[0];
    __syncthreads();

    // Column 0 (one-time, strided, negligible traffic)
    out[p * OUT_COLS] = s0;

    // Register-resident preload of one full chunk (forces batched LDGs -> high MLP)
    float rz1[TILE], rz2[TILE];
    int   rn[TILE];

    #pragma unroll
    for (int s = 0; s < TILE; ++s) {
        const int idx = s * N_PATHS + p;
        rz1[s] = __ldcs(zd + idx);
        rz2[s] = __ldcs(zj + idx);
        rn[s]  = __ldcs(njp + idx);
    }

    float acc = 0.0f;

    for (int c = 0; c < N_CHUNKS; ++c) {
        const int tbase = c * TILE;

        __syncthreads();   // buf free (previous drain complete)

        // --- Compute phase: serial fp32 scan from preloaded regs ---
        #pragma unroll
        for (int s = 0; s < TILE; ++s) {
            int n = rn[s];
            n = (n < JT_SIZE) ? n : (JT_SIZE - 1);
            acc += drift_s[tbase + s] + CDIFF * rz1[s] + jtab[n] * rz2[s];
            buf[tid][s] = s0 * __expf(acc);
        }

        // --- Issue next chunk's loads NOW (overlap with drain below) ---
        if (c + 1 < N_CHUNKS) {
            const int nb = (tbase + TILE) * N_PATHS + p;
            #pragma unroll
            for (int s = 0; s < TILE; ++s) {
                const int idx = nb + s * N_PATHS;
                rz1[s] = __ldcs(zd + idx);
                rz2[s] = __ldcs(zj + idx);
                rn[s]  = __ldcs(njp + idx);
            }
        }

        __syncthreads();   // buf visible to all warps

        // --- Drain: 4 warps x 32 rows, 128B coalesced stores per row ---
        #pragma unroll
        for (int r = 0; r < TILE; ++r) {
            const int row = wid * TILE + r;            // covers all 128 rows
            __stcs(&out[(pbase + row) * OUT_COLS + 1 + tbase + lane], buf[row][lane]);
        }
    }
}

extern "C" void kernel_launch(void* const* d_in, const int* in_sizes, int n_in,
                              void* d_out, int out_size)
{
    const float* S0 = (const float*)d_in[0];
    const float* zd = (const float*)d_in[1];
    const float* zj = (const float*)d_in[2];
    const int*   nj = (const int*)  d_in[3];
    float*       out = (float*)d_out;

    merton_kernel<<<N_PATHS / TPB, TPB>>>(S0, zd, zj, nj, out);
}